// round 1
// baseline (speedup 1.0000x reference)
#include <cuda_runtime.h>

// SO3 projection: for each 4x4 pose, replace the 3x3 block A with
//   Rb = sign(det A) * U_p^T        (U_p = orthogonal polar factor of A)
// and the translation with
//   trans = -sqrt(3) * U_p^T t / ||A||_F
// Row 3 of the output is (0,0,0,1).
//
// U_p is computed with the determinantally-scaled Newton polar iteration:
//   X <- 0.5 * (zeta*X + (1/zeta)*X^{-T}),   zeta = |det X|^{-1/3}
// which converges quadratically; 8 iterations exceed fp32 precision.

#define NEWTON_ITERS 8

__global__ void __launch_bounds__(256)
so3_project_kernel(const float4* __restrict__ in, float4* __restrict__ out, int n)
{
    int b = blockIdx.x * blockDim.x + threadIdx.x;
    if (b >= n) return;

    // Load rows 0..2 (row 3 of the input is unused)
    float4 r0 = in[4 * b + 0];
    float4 r1 = in[4 * b + 1];
    float4 r2 = in[4 * b + 2];

    float a00 = r0.x, a01 = r0.y, a02 = r0.z, t0 = r0.w;
    float a10 = r1.x, a11 = r1.y, a12 = r1.z, t1 = r1.w;
    float a20 = r2.x, a21 = r2.y, a22 = r2.z, t2 = r2.w;

    // det(A) and ||A||_F^2 from the original matrix
    float detA = a00 * (a11 * a22 - a12 * a21)
               - a01 * (a10 * a22 - a12 * a20)
               + a02 * (a10 * a21 - a11 * a20);
    float fro2 = a00 * a00 + a01 * a01 + a02 * a02
               + a10 * a10 + a11 * a11 + a12 * a12
               + a20 * a20 + a21 * a21 + a22 * a22;

    // Newton polar iteration
    float x00 = a00, x01 = a01, x02 = a02;
    float x10 = a10, x11 = a11, x12 = a12;
    float x20 = a20, x21 = a21, x22 = a22;

#pragma unroll
    for (int it = 0; it < NEWTON_ITERS; ++it) {
        // signed cofactor matrix C: X^{-T} = C / det(X)
        float c00 = x11 * x22 - x12 * x21;
        float c01 = x12 * x20 - x10 * x22;
        float c02 = x10 * x21 - x11 * x20;
        float c10 = x02 * x21 - x01 * x22;
        float c11 = x00 * x22 - x02 * x20;
        float c12 = x01 * x20 - x00 * x21;
        float c20 = x01 * x12 - x02 * x11;
        float c21 = x02 * x10 - x00 * x12;
        float c22 = x00 * x11 - x01 * x10;
        float d   = x00 * c00 + x01 * c01 + x02 * c02;

        float ad   = fmaxf(fabsf(d), 1e-30f);
        float zeta = __powf(ad, -0.3333333333f);     // |det(zeta*X)| ~= 1
        float hz   = 0.5f * zeta;
        float izd  = __fdividef(0.5f, zeta * d);     // 0.5 / (zeta * det)

        x00 = hz * x00 + izd * c00;
        x01 = hz * x01 + izd * c01;
        x02 = hz * x02 + izd * c02;
        x10 = hz * x10 + izd * c10;
        x11 = hz * x11 + izd * c11;
        x12 = hz * x12 + izd * c12;
        x20 = hz * x20 + izd * c20;
        x21 = hz * x21 + izd * c21;
        x22 = hz * x22 + izd * c22;
    }

    // X ~= U_p. Rb[i][j] = s * U_p[j][i];  trans_i = -sqrt(3)/fro * (col_i(U_p) . t)
    float s  = (detA < 0.0f) ? -1.0f : 1.0f;
    float ts = -1.7320508075688772f * rsqrtf(fro2);

    float tr0 = ts * (x00 * t0 + x10 * t1 + x20 * t2);
    float tr1 = ts * (x01 * t0 + x11 * t1 + x21 * t2);
    float tr2 = ts * (x02 * t0 + x12 * t1 + x22 * t2);

    out[4 * b + 0] = make_float4(s * x00, s * x10, s * x20, tr0);
    out[4 * b + 1] = make_float4(s * x01, s * x11, s * x21, tr1);
    out[4 * b + 2] = make_float4(s * x02, s * x12, s * x22, tr2);
    out[4 * b + 3] = make_float4(0.0f, 0.0f, 0.0f, 1.0f);
}

extern "C" void kernel_launch(void* const* d_in, const int* in_sizes, int n_in,
                              void* d_out, int out_size)
{
    const int n = in_sizes[0] / 16;          // number of 4x4 matrices
    const int threads = 256;
    const int blocks  = (n + threads - 1) / threads;
    so3_project_kernel<<<blocks, threads>>>(
        (const float4*)d_in[0], (float4*)d_out, n);
}